// round 1
// baseline (speedup 1.0000x reference)
#include <cuda_runtime.h>

#define BATCH 65536
#define NEG 5
#define WARPS_PER_BLOCK 8
#define THREADS (WARPS_PER_BLOCK * 32)
#define NBLOCKS (BATCH / WARPS_PER_BLOCK)   // 8192

__device__ float g_partials[NBLOCKS];

__global__ __launch_bounds__(THREADS) void sgneg_stage1(
    const int* __restrict__ pos_w,
    const int* __restrict__ pos_v,
    const int* __restrict__ neg_v,
    const float4* __restrict__ w_table,   // [VOCAB][32] float4
    const float4* __restrict__ v_table)   // [VOCAB][32] float4
{
    const int lane = threadIdx.x & 31;
    const int wib  = threadIdx.x >> 5;
    const int b    = blockIdx.x * WARPS_PER_BLOCK + wib;

    float acc = 0.0f;

    // Gather indices (uniform per warp — broadcast load)
    const int wi  = pos_w[b];
    const int pvi = pos_v[b];
    int ni[NEG];
#pragma unroll
    for (int k = 0; k < NEG; k++) ni[k] = neg_v[b * NEG + k];

    // Gather rows: each lane one float4 -> 512B coalesced per row
    const float4 w = w_table[(size_t)wi * 32 + lane];
    const float4 p = v_table[(size_t)pvi * 32 + lane];

    float d0 = w.x * p.x + w.y * p.y + w.z * p.z + w.w * p.w;
    float dn[NEG];
#pragma unroll
    for (int k = 0; k < NEG; k++) {
        const float4 nv = v_table[(size_t)ni[k] * 32 + lane];
        dn[k] = w.x * nv.x + w.y * nv.y + w.z * nv.z + w.w * nv.w;
    }

    // Warp butterfly reduction of all 6 dots
#pragma unroll
    for (int off = 16; off > 0; off >>= 1) {
        d0 += __shfl_xor_sync(0xFFFFFFFFu, d0, off);
#pragma unroll
        for (int k = 0; k < NEG; k++)
            dn[k] += __shfl_xor_sync(0xFFFFFFFFu, dn[k], off);
    }

    if (lane == 0) {
        // log_sigmoid(x) = -log1p(exp(-x)); scores clipped to [-10, 10]
        float s = fminf(fmaxf(d0, -10.0f), 10.0f);
        acc = -log1pf(expf(-s));                 // log_sigmoid(score1)
#pragma unroll
        for (int k = 0; k < NEG; k++) {
            float t = fminf(fmaxf(dn[k], -10.0f), 10.0f);
            acc += -log1pf(expf(t));             // log_sigmoid(-score2)
        }
    }

    // Block reduce the 8 lane-0 values
    __shared__ float sh[WARPS_PER_BLOCK];
    if (lane == 0) sh[wib] = acc;
    __syncthreads();
    if (threadIdx.x == 0) {
        float s = 0.0f;
#pragma unroll
        for (int i = 0; i < WARPS_PER_BLOCK; i++) s += sh[i];
        g_partials[blockIdx.x] = s;
    }
}

__global__ __launch_bounds__(256) void sgneg_stage2(float* __restrict__ out)
{
    __shared__ double sh[256];
    double s = 0.0;
    for (int i = threadIdx.x; i < NBLOCKS; i += 256)
        s += (double)g_partials[i];
    sh[threadIdx.x] = s;
    __syncthreads();
#pragma unroll
    for (int st = 128; st > 0; st >>= 1) {
        if (threadIdx.x < st) sh[threadIdx.x] += sh[threadIdx.x + st];
        __syncthreads();
    }
    if (threadIdx.x == 0) out[0] = (float)(-sh[0]);
}

extern "C" void kernel_launch(void* const* d_in, const int* in_sizes, int n_in,
                              void* d_out, int out_size)
{
    const int*    pos_w   = (const int*)d_in[0];
    const int*    pos_v   = (const int*)d_in[1];
    const int*    neg_v   = (const int*)d_in[2];
    const float4* w_table = (const float4*)d_in[3];
    const float4* v_table = (const float4*)d_in[4];
    float*        out     = (float*)d_out;

    sgneg_stage1<<<NBLOCKS, THREADS>>>(pos_w, pos_v, neg_v, w_table, v_table);
    sgneg_stage2<<<1, 256>>>(out);
}

// round 2
// speedup vs baseline: 1.0164x; 1.0164x over previous
#include <cuda_runtime.h>

#define BATCH 65536
#define NEG 5
#define WARPS_PER_BLOCK 8
#define THREADS (WARPS_PER_BLOCK * 32)
#define GRID 1184                       // 148 SMs * 8 blocks -> 64 warps/SM
#define TOTAL_WARPS (GRID * WARPS_PER_BLOCK)

__device__ float g_partials[GRID];
__device__ unsigned int g_done_count = 0;

__global__ __launch_bounds__(THREADS) void sgneg_fused(
    const int* __restrict__ pos_w,
    const int* __restrict__ pos_v,
    const int* __restrict__ neg_v,
    const float4* __restrict__ w_table,   // [VOCAB][32] float4
    const float4* __restrict__ v_table,   // [VOCAB][32] float4
    float* __restrict__ out)
{
    const int lane = threadIdx.x & 31;
    const int wib  = threadIdx.x >> 5;
    const int gw   = blockIdx.x * WARPS_PER_BLOCK + wib;   // global warp id

    float acc = 0.0f;   // meaningful on lane 0 only

    for (int b = gw; b < BATCH; b += TOTAL_WARPS) {
        // Indices (uniform per warp — broadcast loads)
        const int wi  = pos_w[b];
        const int pvi = pos_v[b];
        int ni[NEG];
#pragma unroll
        for (int k = 0; k < NEG; k++) ni[k] = neg_v[b * NEG + k];

        // Gather rows: one float4/lane -> 512B coalesced per row
        const float4 w = w_table[(size_t)wi * 32 + lane];
        const float4 p = v_table[(size_t)pvi * 32 + lane];

        float d0 = w.x * p.x + w.y * p.y + w.z * p.z + w.w * p.w;
        float dn[NEG];
#pragma unroll
        for (int k = 0; k < NEG; k++) {
            const float4 nv = v_table[(size_t)ni[k] * 32 + lane];
            dn[k] = w.x * nv.x + w.y * nv.y + w.z * nv.z + w.w * nv.w;
        }

        // Warp butterfly reduction of all 6 dots
#pragma unroll
        for (int off = 16; off > 0; off >>= 1) {
            d0 += __shfl_xor_sync(0xFFFFFFFFu, d0, off);
#pragma unroll
            for (int k = 0; k < NEG; k++)
                dn[k] += __shfl_xor_sync(0xFFFFFFFFu, dn[k], off);
        }

        if (lane == 0) {
            // log_sigmoid(x) = -log1p(exp(-x)); scores clipped to [-10, 10]
            float s = fminf(fmaxf(d0, -10.0f), 10.0f);
            acc += -log1pf(expf(-s));                // log_sigmoid(score1)
#pragma unroll
            for (int k = 0; k < NEG; k++) {
                float t = fminf(fmaxf(dn[k], -10.0f), 10.0f);
                acc += -log1pf(expf(t));             // log_sigmoid(-score2)
            }
        }
    }

    // Block reduction of the 8 lane-0 accumulators
    __shared__ float sh[WARPS_PER_BLOCK];
    if (lane == 0) sh[wib] = acc;
    __syncthreads();

    __shared__ bool is_last;
    if (threadIdx.x == 0) {
        float s = 0.0f;
#pragma unroll
        for (int i = 0; i < WARPS_PER_BLOCK; i++) s += sh[i];
        g_partials[blockIdx.x] = s;
        __threadfence();
        unsigned int old = atomicAdd(&g_done_count, 1u);
        is_last = (old == (unsigned int)(GRID - 1));
    }
    __syncthreads();

    // Last block performs the final reduction
    if (is_last) {
        __shared__ double shd[THREADS];
        double s = 0.0;
        for (int i = threadIdx.x; i < GRID; i += THREADS)
            s += (double)g_partials[i];
        shd[threadIdx.x] = s;
        __syncthreads();
#pragma unroll
        for (int st = THREADS / 2; st > 0; st >>= 1) {
            if (threadIdx.x < st) shd[threadIdx.x] += shd[threadIdx.x + st];
            __syncthreads();
        }
        if (threadIdx.x == 0) {
            out[0] = (float)(-shd[0]);
            g_done_count = 0;   // reset for next graph replay
        }
    }
}

extern "C" void kernel_launch(void* const* d_in, const int* in_sizes, int n_in,
                              void* d_out, int out_size)
{
    const int*    pos_w   = (const int*)d_in[0];
    const int*    pos_v   = (const int*)d_in[1];
    const int*    neg_v   = (const int*)d_in[2];
    const float4* w_table = (const float4*)d_in[3];
    const float4* v_table = (const float4*)d_in[4];
    float*        out     = (float*)d_out;

    sgneg_fused<<<GRID, THREADS>>>(pos_w, pos_v, neg_v, w_table, v_table, out);
}

// round 3
// speedup vs baseline: 1.2049x; 1.1855x over previous
#include <cuda_runtime.h>

#define BATCH 65536
#define NEG 5
#define WPB 8
#define THREADS 256
#define GRID 1184                 // 148 SMs * 8 blocks
#define TW (GRID * WPB)           // 9472 warps

__device__ float g_partials[GRID];
__device__ unsigned int g_done_count = 0;

__device__ __forceinline__ float elem_term(
    int b, int lane,
    const int* __restrict__ pos_w, const int* __restrict__ pos_v,
    const int* __restrict__ neg_v,
    const float4* __restrict__ w_table, const float4* __restrict__ v_table)
{
    // 32-bit row offsets (max 100000*32 = 3.2M, fits easily)
    const int wi  = pos_w[b] << 5;
    const int pvi = pos_v[b] << 5;
    const int ni0 = neg_v[b * NEG + 0] << 5;
    const int ni1 = neg_v[b * NEG + 1] << 5;
    const int ni2 = neg_v[b * NEG + 2] << 5;
    const int ni3 = neg_v[b * NEG + 3] << 5;
    const int ni4 = neg_v[b * NEG + 4] << 5;

    // 7 independent 512B coalesced gathers
    const float4 w  = w_table[wi  + lane];
    const float4 p  = v_table[pvi + lane];
    const float4 n0 = v_table[ni0 + lane];
    const float4 n1 = v_table[ni1 + lane];
    const float4 n2 = v_table[ni2 + lane];
    const float4 n3 = v_table[ni3 + lane];
    const float4 n4 = v_table[ni4 + lane];

    float d0 = w.x*p.x  + w.y*p.y  + w.z*p.z  + w.w*p.w;
    float d1 = w.x*n0.x + w.y*n0.y + w.z*n0.z + w.w*n0.w;
    float d2 = w.x*n1.x + w.y*n1.y + w.z*n1.z + w.w*n1.w;
    float d3 = w.x*n2.x + w.y*n2.y + w.z*n2.z + w.w*n2.w;
    float d4 = w.x*n3.x + w.y*n3.y + w.z*n3.z + w.w*n3.w;
    float d5 = w.x*n4.x + w.y*n4.y + w.z*n4.z + w.w*n4.w;

#pragma unroll
    for (int off = 16; off > 0; off >>= 1) {
        d0 += __shfl_xor_sync(0xFFFFFFFFu, d0, off);
        d1 += __shfl_xor_sync(0xFFFFFFFFu, d1, off);
        d2 += __shfl_xor_sync(0xFFFFFFFFu, d2, off);
        d3 += __shfl_xor_sync(0xFFFFFFFFu, d3, off);
        d4 += __shfl_xor_sync(0xFFFFFFFFu, d4, off);
        d5 += __shfl_xor_sync(0xFFFFFFFFu, d5, off);
    }

    // Every lane now holds all 6 full sums. Lane k (k<6) handles term k.
    float x = d0;
    x = (lane == 1) ? d1 : x;
    x = (lane == 2) ? d2 : x;
    x = (lane == 3) ? d3 : x;
    x = (lane == 4) ? d4 : x;
    x = (lane == 5) ? d5 : x;

    x = fminf(fmaxf(x, -10.0f), 10.0f);
    if (lane != 0) x = -x;                 // negatives get logsigmoid(-score)
    float t = -log1pf(expf(-x));           // log_sigmoid(x)
    return (lane < 6) ? t : 0.0f;
}

__global__ __launch_bounds__(THREADS) void sgneg_fused(
    const int* __restrict__ pos_w,
    const int* __restrict__ pos_v,
    const int* __restrict__ neg_v,
    const float4* __restrict__ w_table,
    const float4* __restrict__ v_table,
    float* __restrict__ out)
{
    const int lane = threadIdx.x & 31;
    const int wib  = threadIdx.x >> 5;
    const int gw   = blockIdx.x * WPB + wib;

    float acc = 0.0f;   // per-thread partial (lanes 0..5 carry real terms)

    int b = gw;
    // 2x unrolled grid-stride: 14 independent gathers in flight per warp
    while (b + TW < BATCH) {
        acc += elem_term(b,      lane, pos_w, pos_v, neg_v, w_table, v_table);
        acc += elem_term(b + TW, lane, pos_w, pos_v, neg_v, w_table, v_table);
        b += 2 * TW;
    }
    if (b < BATCH)
        acc += elem_term(b, lane, pos_w, pos_v, neg_v, w_table, v_table);

    // One warp-level reduction of acc at the very end
#pragma unroll
    for (int off = 16; off > 0; off >>= 1)
        acc += __shfl_xor_sync(0xFFFFFFFFu, acc, off);

    __shared__ float sh[WPB];
    if (lane == 0) sh[wib] = acc;
    __syncthreads();

    __shared__ bool is_last;
    if (threadIdx.x == 0) {
        float s = 0.0f;
#pragma unroll
        for (int i = 0; i < WPB; i++) s += sh[i];
        g_partials[blockIdx.x] = s;
        __threadfence();
        unsigned int old = atomicAdd(&g_done_count, 1u);
        is_last = (old == (unsigned int)(GRID - 1));
    }
    __syncthreads();

    if (is_last) {
        __shared__ double shd[THREADS];
        double s = 0.0;
        for (int i = threadIdx.x; i < GRID; i += THREADS)
            s += (double)g_partials[i];
        shd[threadIdx.x] = s;
        __syncthreads();
#pragma unroll
        for (int st = THREADS / 2; st > 0; st >>= 1) {
            if (threadIdx.x < st) shd[threadIdx.x] += shd[threadIdx.x + st];
            __syncthreads();
        }
        if (threadIdx.x == 0) {
            out[0] = (float)(-shd[0]);
            g_done_count = 0;   // reset for next graph replay
        }
    }
}

extern "C" void kernel_launch(void* const* d_in, const int* in_sizes, int n_in,
                              void* d_out, int out_size)
{
    const int*    pos_w   = (const int*)d_in[0];
    const int*    pos_v   = (const int*)d_in[1];
    const int*    neg_v   = (const int*)d_in[2];
    const float4* w_table = (const float4*)d_in[3];
    const float4* v_table = (const float4*)d_in[4];
    float*        out     = (float*)d_out;

    sgneg_fused<<<GRID, THREADS>>>(pos_w, pos_v, neg_v, w_table, v_table, out);
}

// round 4
// speedup vs baseline: 1.6333x; 1.3556x over previous
#include <cuda_runtime.h>

#define BATCH 65536
#define NEG 5
#define WPB 8
#define THREADS 256
#define GRID 888                  // 148 SMs * 6 blocks -> exactly one wave at 40 regs
#define TW (GRID * WPB)           // 7104 warps

__device__ float g_partials[GRID];
__device__ unsigned int g_done_count = 0;

__device__ __forceinline__ float elem_term(
    int b, int lane,
    const int* __restrict__ pos_w, const int* __restrict__ pos_v,
    const int* __restrict__ neg_v,
    const float4* __restrict__ w_table, const float4* __restrict__ v_table)
{
    // 32-bit row offsets (max 100000*32 = 3.2M float4)
    const int wi  = pos_w[b] << 5;
    const int pvi = pos_v[b] << 5;
    const int ni0 = neg_v[b * NEG + 0] << 5;
    const int ni1 = neg_v[b * NEG + 1] << 5;
    const int ni2 = neg_v[b * NEG + 2] << 5;
    const int ni3 = neg_v[b * NEG + 3] << 5;
    const int ni4 = neg_v[b * NEG + 4] << 5;

    // 7 independent 512B coalesced gathers
    const float4 w  = w_table[wi  + lane];
    const float4 p  = v_table[pvi + lane];
    const float4 n0 = v_table[ni0 + lane];
    const float4 n1 = v_table[ni1 + lane];
    const float4 n2 = v_table[ni2 + lane];
    const float4 n3 = v_table[ni3 + lane];
    const float4 n4 = v_table[ni4 + lane];

    float d0 = w.x*p.x  + w.y*p.y  + w.z*p.z  + w.w*p.w;
    float d1 = w.x*n0.x + w.y*n0.y + w.z*n0.z + w.w*n0.w;
    float d2 = w.x*n1.x + w.y*n1.y + w.z*n1.z + w.w*n1.w;
    float d3 = w.x*n2.x + w.y*n2.y + w.z*n2.z + w.w*n2.w;
    float d4 = w.x*n3.x + w.y*n3.y + w.z*n3.z + w.w*n3.w;
    float d5 = w.x*n4.x + w.y*n4.y + w.z*n4.z + w.w*n4.w;

    // Packed 6-value warp reduction: 13 shuffles instead of 30.
    const unsigned FULL = 0xFFFFFFFFu;
    float t, u;
    // offset 16: merge pairs into lane halves (bit4 selects member)
    t = __shfl_xor_sync(FULL, d0, 16);
    u = __shfl_xor_sync(FULL, d1, 16);
    float e0 = (lane & 16) ? d1 + u : d0 + t;
    t = __shfl_xor_sync(FULL, d2, 16);
    u = __shfl_xor_sync(FULL, d3, 16);
    float e1 = (lane & 16) ? d3 + u : d2 + t;
    t = __shfl_xor_sync(FULL, d4, 16);
    u = __shfl_xor_sync(FULL, d5, 16);
    float e2 = (lane & 16) ? d5 + u : d4 + t;
    // offset 8: merge (e0,e1) -> f0 (bit3 selects); e2 plain butterfly
    t = __shfl_xor_sync(FULL, e0, 8);
    u = __shfl_xor_sync(FULL, e1, 8);
    float f0 = (lane & 8) ? e1 + u : e0 + t;
    e2 += __shfl_xor_sync(FULL, e2, 8);
    // offset 4: merge (f0,e2) -> g (bit2 selects)
    t = __shfl_xor_sync(FULL, f0, 4);
    u = __shfl_xor_sync(FULL, e2, 4);
    float g = (lane & 4) ? e2 + u : f0 + t;
    // finish within 4-lane segments
    g += __shfl_xor_sync(FULL, g, 2);
    g += __shfl_xor_sync(FULL, g, 1);

    // Unique owner lanes: 0->d0(pos), 16->d1, 8->d2, 24->d3, 4->d4, 20->d5
    const bool active = ((lane & 3) == 0) && !((lane & 4) && (lane & 8));
    float x = fminf(fmaxf(g, -10.0f), 10.0f);
    if (lane != 0) x = -x;                        // negatives: logsigmoid(-score)
    // log_sigmoid(x) = -log(1 + exp(-x)); x in [-10,10] so fast-math is safe
    float term = -__logf(1.0f + __expf(-x));
    return active ? term : 0.0f;
}

__global__ __launch_bounds__(THREADS, 6) void sgneg_fused(
    const int* __restrict__ pos_w,
    const int* __restrict__ pos_v,
    const int* __restrict__ neg_v,
    const float4* __restrict__ w_table,
    const float4* __restrict__ v_table,
    float* __restrict__ out)
{
    const int lane = threadIdx.x & 31;
    const int wib  = threadIdx.x >> 5;
    const int gw   = blockIdx.x * WPB + wib;

    float acc = 0.0f;

    int b = gw;
    while (b + TW < BATCH) {      // 2x unrolled: 14 gathers in flight
        acc += elem_term(b,      lane, pos_w, pos_v, neg_v, w_table, v_table);
        acc += elem_term(b + TW, lane, pos_w, pos_v, neg_v, w_table, v_table);
        b += 2 * TW;
    }
    if (b < BATCH)
        acc += elem_term(b, lane, pos_w, pos_v, neg_v, w_table, v_table);

    // Single end-of-kernel warp reduction
#pragma unroll
    for (int off = 16; off > 0; off >>= 1)
        acc += __shfl_xor_sync(0xFFFFFFFFu, acc, off);

    __shared__ float sh[WPB];
    if (lane == 0) sh[wib] = acc;
    __syncthreads();

    __shared__ bool is_last;
    if (threadIdx.x == 0) {
        float s = 0.0f;
#pragma unroll
        for (int i = 0; i < WPB; i++) s += sh[i];
        g_partials[blockIdx.x] = s;
        __threadfence();
        unsigned int old = atomicAdd(&g_done_count, 1u);
        is_last = (old == (unsigned int)(GRID - 1));
    }
    __syncthreads();

    if (is_last) {
        __shared__ double shd[THREADS];
        double s = 0.0;
        for (int i = threadIdx.x; i < GRID; i += THREADS)
            s += (double)g_partials[i];
        shd[threadIdx.x] = s;
        __syncthreads();
#pragma unroll
        for (int st = THREADS / 2; st > 0; st >>= 1) {
            if (threadIdx.x < st) shd[threadIdx.x] += shd[threadIdx.x + st];
            __syncthreads();
        }
        if (threadIdx.x == 0) {
            out[0] = (float)(-shd[0]);
            g_done_count = 0;   // reset for next graph replay
        }
    }
}

extern "C" void kernel_launch(void* const* d_in, const int* in_sizes, int n_in,
                              void* d_out, int out_size)
{
    const int*    pos_w   = (const int*)d_in[0];
    const int*    pos_v   = (const int*)d_in[1];
    const int*    neg_v   = (const int*)d_in[2];
    const float4* w_table = (const float4*)d_in[3];
    const float4* v_table = (const float4*)d_in[4];
    float*        out     = (float*)d_out;

    sgneg_fused<<<GRID, THREADS>>>(pos_w, pos_v, neg_v, w_table, v_table, out);
}